// round 2
// baseline (speedup 1.0000x reference)
#include <cuda_runtime.h>
#include <math_constants.h>

#define BB 64
#define TT 4096
#define QDIM 1024
#define ADIM 256
#define MASK_VAL (-1e30f)

// Scratch (allocation-free rule: device globals)
__device__ float g_pq[BB * ADIM];        // processed query (B, AD)
__device__ float g_energies[BB * TT];    // masked energies (B, T)

__device__ __forceinline__ float tanh_fast(float x) {
    float y;
    asm("tanh.approx.f32 %0, %1;" : "=f"(y) : "f"(x));
    return y;
}

// ---------------------------------------------------------------------------
// Kernel 1: pq[b,d] = dot(query[b,:], Wq[d,:])   (64 x 256 outputs, K=1024)
// One warp per output dot product; float4 coalesced loads.
// ---------------------------------------------------------------------------
__global__ void __launch_bounds__(256) pq_kernel(const float* __restrict__ query,
                                                 const float* __restrict__ Wq) {
    const int lane = threadIdx.x & 31;
    const int warp = threadIdx.x >> 5;
    const int gw = blockIdx.x * 8 + warp;          // 0 .. 16383
    const int b = gw >> 8;                         // / 256
    const int d = gw & 255;

    const float4* q4 = reinterpret_cast<const float4*>(query + (size_t)b * QDIM);
    const float4* w4 = reinterpret_cast<const float4*>(Wq + (size_t)d * QDIM);

    float s = 0.f;
#pragma unroll
    for (int k = 0; k < 8; ++k) {                  // 1024/4 = 256 float4, 32 lanes
        float4 a = q4[lane + 32 * k];
        float4 w = w4[lane + 32 * k];
        s += a.x * w.x + a.y * w.y + a.z * w.z + a.w * w.w;
    }
#pragma unroll
    for (int off = 16; off > 0; off >>= 1)
        s += __shfl_xor_sync(0xffffffffu, s, off);

    if (lane == 0) g_pq[b * ADIM + d] = s;
}

// ---------------------------------------------------------------------------
// Kernel 2: energies[b,t] = sum_d tanh(pq[b,d] + pm[b,t,d]) * v[d]; mask.
// One warp per (b,t) row, 16 rows per warp. Each lane: 2x float4 per row.
// This streams the 268 MB of processed_memory -> memory-bound target.
// mask arrives as int32 (harness normalizes bool -> int32).
// ---------------------------------------------------------------------------
#define TPW 16           // t-rows per warp
__global__ void __launch_bounds__(256) energies_kernel(
        const float* __restrict__ pm,
        const int* __restrict__ mask,
        const float* __restrict__ v) {
    const int lane = threadIdx.x & 31;
    const int warp = threadIdx.x >> 5;
    const int gw = blockIdx.x * 8 + warp;          // global warp id
    const int warpsPerB = TT / TPW;                // 256
    const int b = gw / warpsPerB;
    const int t0 = (gw % warpsPerB) * TPW;

    // Register-resident pq row and v (8 floats each per lane)
    const float4* pq4 = reinterpret_cast<const float4*>(g_pq + b * ADIM);
    const float4* v4 = reinterpret_cast<const float4*>(v);
    const float4 p0 = pq4[lane], p1 = pq4[lane + 32];
    const float4 v0 = v4[lane], v1 = v4[lane + 32];

#pragma unroll 2
    for (int i = 0; i < TPW; ++i) {
        const int t = t0 + i;
        const float4* x4 = reinterpret_cast<const float4*>(
            pm + ((size_t)b * TT + t) * ADIM);
        float4 a = x4[lane];
        float4 c = x4[lane + 32];

        float s = tanh_fast(a.x + p0.x) * v0.x;
        s += tanh_fast(a.y + p0.y) * v0.y;
        s += tanh_fast(a.z + p0.z) * v0.z;
        s += tanh_fast(a.w + p0.w) * v0.w;
        s += tanh_fast(c.x + p1.x) * v1.x;
        s += tanh_fast(c.y + p1.y) * v1.y;
        s += tanh_fast(c.z + p1.z) * v1.z;
        s += tanh_fast(c.w + p1.w) * v1.w;

#pragma unroll
        for (int off = 16; off > 0; off >>= 1)
            s += __shfl_xor_sync(0xffffffffu, s, off);

        if (lane == 0) {
            const size_t idx = (size_t)b * TT + t;
            g_energies[idx] = (mask[idx] != 0) ? MASK_VAL : s;
        }
    }
}

// ---------------------------------------------------------------------------
// Kernel 3: row softmax over T=4096. One block (1024 thr) per batch row.
// ---------------------------------------------------------------------------
__global__ void __launch_bounds__(1024) softmax_kernel(float* __restrict__ out) {
    const int b = blockIdx.x;
    const int tid = threadIdx.x;
    const int lane = tid & 31;
    const int warp = tid >> 5;
    __shared__ float red[32];
    __shared__ float bcast;

    float e[4];
    float m = -CUDART_INF_F;
#pragma unroll
    for (int i = 0; i < 4; ++i) {
        e[i] = g_energies[(size_t)b * TT + i * 1024 + tid];
        m = fmaxf(m, e[i]);
    }
#pragma unroll
    for (int off = 16; off > 0; off >>= 1)
        m = fmaxf(m, __shfl_xor_sync(0xffffffffu, m, off));
    if (lane == 0) red[warp] = m;
    __syncthreads();
    if (warp == 0) {
        float mm = red[lane];
#pragma unroll
        for (int off = 16; off > 0; off >>= 1)
            mm = fmaxf(mm, __shfl_xor_sync(0xffffffffu, mm, off));
        if (lane == 0) bcast = mm;
    }
    __syncthreads();
    m = bcast;

    float s = 0.f;
#pragma unroll
    for (int i = 0; i < 4; ++i) {
        e[i] = __expf(e[i] - m);
        s += e[i];
    }
#pragma unroll
    for (int off = 16; off > 0; off >>= 1)
        s += __shfl_xor_sync(0xffffffffu, s, off);
    if (lane == 0) red[warp] = s;
    __syncthreads();
    if (warp == 0) {
        float ss = red[lane];
#pragma unroll
        for (int off = 16; off > 0; off >>= 1)
            ss += __shfl_xor_sync(0xffffffffu, ss, off);
        if (lane == 0) bcast = ss;
    }
    __syncthreads();
    const float inv = 1.0f / bcast;

#pragma unroll
    for (int i = 0; i < 4; ++i)
        out[(size_t)b * TT + i * 1024 + tid] = e[i] * inv;
}

// ---------------------------------------------------------------------------
extern "C" void kernel_launch(void* const* d_in, const int* in_sizes, int n_in,
                              void* d_out, int out_size) {
    const float* query = (const float*)d_in[0];          // (64, 1024) f32
    const float* pm    = (const float*)d_in[1];          // (64, 4096, 256) f32
    const int*   mask  = (const int*)d_in[2];            // (64, 4096) bool -> int32
    const float* Wq    = (const float*)d_in[3];          // (256, 1024) f32
    const float* v     = (const float*)d_in[4];          // (256,) f32
    float* out = (float*)d_out;                          // (64, 4096) f32

    // K1: 64*256 warps / 8 per block = 2048 blocks
    pq_kernel<<<2048, 256>>>(query, Wq);
    // K2: 64*4096/16 warps / 8 per block = 2048 blocks
    energies_kernel<<<2048, 256>>>(pm, mask, v);
    // K3: one block per batch row
    softmax_kernel<<<BB, 1024>>>(out);
}

// round 3
// speedup vs baseline: 1.0354x; 1.0354x over previous
#include <cuda_runtime.h>
#include <math_constants.h>

#define BB 64
#define TT 4096
#define QDIM 1024
#define ADIM 256
#define MASK_VAL (-1e30f)

// Scratch (allocation-free rule: device globals)
__device__ float g_pq[BB * ADIM];        // processed query (B, AD)
__device__ float g_energies[BB * TT];    // masked energies (B, T)

__device__ __forceinline__ float tanh_fast(float x) {
    float y;
    asm("tanh.approx.f32 %0, %1;" : "=f"(y) : "f"(x));
    return y;
}

// ---------------------------------------------------------------------------
// Kernel 1: pq[b,d] = dot(query[b,:], Wq[d,:])   (64 x 256 outputs, K=1024)
// Tiled for reuse: block = 16 warps computes (8 b x 16 d) tile.
//   - query tile (8 x 1024 f = 32 KB) staged in smem, read 16x from there
//   - each warp holds one Wq row in registers, reused across the 8 b rows
// L2 traffic: 64 MB (old warp-per-output scheme) -> 12 MB.
// Grid = (64/8 b-tiles) x (256/16 d-tiles) = 128 blocks.
// ---------------------------------------------------------------------------
#define PQ_BT 8
#define PQ_DT 16
__global__ void __launch_bounds__(512) pq_kernel(const float* __restrict__ query,
                                                 const float* __restrict__ Wq) {
    __shared__ float sq[PQ_BT * QDIM];             // 32 KB

    const int lane = threadIdx.x & 31;
    const int warp = threadIdx.x >> 5;             // 0..15
    const int btile = blockIdx.x >> 4;             // 0..7
    const int dtile = blockIdx.x & 15;             // 0..15
    const int b0 = btile * PQ_BT;
    const int d  = dtile * PQ_DT + warp;

    // Cooperative load of query tile: 8*1024 f = 2048 float4 / 512 thr = 4 each
    {
        const float4* qg = reinterpret_cast<const float4*>(query + (size_t)b0 * QDIM);
        float4* sq4 = reinterpret_cast<float4*>(sq);
#pragma unroll
        for (int i = 0; i < 4; ++i)
            sq4[threadIdx.x + 512 * i] = qg[threadIdx.x + 512 * i];
    }

    // Wq row for this warp's d, register-resident (8 float4 per lane)
    const float4* w4 = reinterpret_cast<const float4*>(Wq + (size_t)d * QDIM);
    float4 w[8];
#pragma unroll
    for (int k = 0; k < 8; ++k) w[k] = w4[lane + 32 * k];

    __syncthreads();

#pragma unroll
    for (int bi = 0; bi < PQ_BT; ++bi) {
        const float4* q4 = reinterpret_cast<const float4*>(sq + bi * QDIM);
        float s = 0.f;
#pragma unroll
        for (int k = 0; k < 8; ++k) {
            float4 a = q4[lane + 32 * k];
            s += a.x * w[k].x + a.y * w[k].y + a.z * w[k].z + a.w * w[k].w;
        }
#pragma unroll
        for (int off = 16; off > 0; off >>= 1)
            s += __shfl_xor_sync(0xffffffffu, s, off);
        if (lane == 0) g_pq[(b0 + bi) * ADIM + d] = s;
    }
}

// ---------------------------------------------------------------------------
// Kernel 2: energies[b,t] = sum_d tanh(pq[b,d] + pm[b,t,d]) * v[d]; mask.
// One warp per (b,t) row, 16 rows per warp. Each lane: 2x float4 per row.
// Streams the 268 MB of processed_memory -> memory-bound.
// mask arrives as int32 (harness normalizes bool -> int32); its load is
// issued before the shfl-reduce chain so the latency overlaps.
// ---------------------------------------------------------------------------
#define TPW 16           // t-rows per warp
__global__ void __launch_bounds__(256) energies_kernel(
        const float* __restrict__ pm,
        const int* __restrict__ mask,
        const float* __restrict__ v) {
    const int lane = threadIdx.x & 31;
    const int warp = threadIdx.x >> 5;
    const int gw = blockIdx.x * 8 + warp;          // global warp id
    const int warpsPerB = TT / TPW;                // 256
    const int b = gw / warpsPerB;
    const int t0 = (gw % warpsPerB) * TPW;

    // Register-resident pq row and v (8 floats each per lane)
    const float4* pq4 = reinterpret_cast<const float4*>(g_pq + b * ADIM);
    const float4* v4 = reinterpret_cast<const float4*>(v);
    const float4 p0 = pq4[lane], p1 = pq4[lane + 32];
    const float4 v0 = v4[lane], v1 = v4[lane + 32];

#pragma unroll 2
    for (int i = 0; i < TPW; ++i) {
        const int t = t0 + i;
        const size_t idx = (size_t)b * TT + t;
        const float4* x4 = reinterpret_cast<const float4*>(pm + idx * ADIM);
        float4 a = x4[lane];
        float4 c = x4[lane + 32];

        // Issue the (lane-0) mask load early; latency hides under tanh+shfl.
        int mk = 0;
        if (lane == 0) mk = mask[idx];

        float s = tanh_fast(a.x + p0.x) * v0.x;
        s += tanh_fast(a.y + p0.y) * v0.y;
        s += tanh_fast(a.z + p0.z) * v0.z;
        s += tanh_fast(a.w + p0.w) * v0.w;
        s += tanh_fast(c.x + p1.x) * v1.x;
        s += tanh_fast(c.y + p1.y) * v1.y;
        s += tanh_fast(c.z + p1.z) * v1.z;
        s += tanh_fast(c.w + p1.w) * v1.w;

#pragma unroll
        for (int off = 16; off > 0; off >>= 1)
            s += __shfl_xor_sync(0xffffffffu, s, off);

        if (lane == 0)
            g_energies[idx] = mk ? MASK_VAL : s;
    }
}

// ---------------------------------------------------------------------------
// Kernel 3: row softmax over T=4096. One block (1024 thr) per batch row.
// ---------------------------------------------------------------------------
__global__ void __launch_bounds__(1024) softmax_kernel(float* __restrict__ out) {
    const int b = blockIdx.x;
    const int tid = threadIdx.x;
    const int lane = tid & 31;
    const int warp = tid >> 5;
    __shared__ float red[32];
    __shared__ float bcast;

    float e[4];
    float m = -CUDART_INF_F;
#pragma unroll
    for (int i = 0; i < 4; ++i) {
        e[i] = g_energies[(size_t)b * TT + i * 1024 + tid];
        m = fmaxf(m, e[i]);
    }
#pragma unroll
    for (int off = 16; off > 0; off >>= 1)
        m = fmaxf(m, __shfl_xor_sync(0xffffffffu, m, off));
    if (lane == 0) red[warp] = m;
    __syncthreads();
    if (warp == 0) {
        float mm = red[lane];
#pragma unroll
        for (int off = 16; off > 0; off >>= 1)
            mm = fmaxf(mm, __shfl_xor_sync(0xffffffffu, mm, off));
        if (lane == 0) bcast = mm;
    }
    __syncthreads();
    m = bcast;

    float s = 0.f;
#pragma unroll
    for (int i = 0; i < 4; ++i) {
        e[i] = __expf(e[i] - m);
        s += e[i];
    }
#pragma unroll
    for (int off = 16; off > 0; off >>= 1)
        s += __shfl_xor_sync(0xffffffffu, s, off);
    if (lane == 0) red[warp] = s;
    __syncthreads();
    if (warp == 0) {
        float ss = red[lane];
#pragma unroll
        for (int off = 16; off > 0; off >>= 1)
            ss += __shfl_xor_sync(0xffffffffu, ss, off);
        if (lane == 0) bcast = ss;
    }
    __syncthreads();
    const float inv = 1.0f / bcast;

#pragma unroll
    for (int i = 0; i < 4; ++i)
        out[(size_t)b * TT + i * 1024 + tid] = e[i] * inv;
}

// ---------------------------------------------------------------------------
extern "C" void kernel_launch(void* const* d_in, const int* in_sizes, int n_in,
                              void* d_out, int out_size) {
    const float* query = (const float*)d_in[0];          // (64, 1024) f32
    const float* pm    = (const float*)d_in[1];          // (64, 4096, 256) f32
    const int*   mask  = (const int*)d_in[2];            // (64, 4096) bool -> int32
    const float* Wq    = (const float*)d_in[3];          // (256, 1024) f32
    const float* v     = (const float*)d_in[4];          // (256,) f32
    float* out = (float*)d_out;                          // (64, 4096) f32

    // K1: (8 b-tiles) x (16 d-tiles) = 128 blocks, 512 threads
    pq_kernel<<<128, 512>>>(query, Wq);
    // K2: 64*4096/16 warps / 8 per block = 2048 blocks
    energies_kernel<<<2048, 256>>>(pm, mask, v);
    // K3: one block per batch row
    softmax_kernel<<<BB, 1024>>>(out);
}

// round 4
// speedup vs baseline: 1.4139x; 1.3656x over previous
#include <cuda_runtime.h>
#include <math_constants.h>

#define BB 64
#define TT 4096
#define QDIM 1024
#define ADIM 256
#define MASK_VAL (-1e30f)

// Scratch (allocation-free rule: device globals)
__device__ float g_pq[BB * ADIM];        // processed query (B, AD)
__device__ float g_energies[BB * TT];    // masked energies (B, T)

__device__ __forceinline__ float tanh_fast(float x) {
    float y;
    asm("tanh.approx.f32 %0, %1;" : "=f"(y) : "f"(x));
    return y;
}

// ---------------------------------------------------------------------------
// Kernel 1: pq[b,d] = dot(query[b,:], Wq[d,:])   (64 x 256, K=1024)
// Block = 16 warps, tile (8 b x 32 d); each warp owns TWO Wq rows in
// registers (d and d+16 of the tile), so every query LDS.128 feeds two
// FMA chains and the two shfl reductions overlap (ILP).
// Grid = (64/8) x (256/32) = 64 blocks.
// ---------------------------------------------------------------------------
#define PQ_BT 8
__global__ void __launch_bounds__(512) pq_kernel(const float* __restrict__ query,
                                                 const float* __restrict__ Wq) {
    __shared__ float sq[PQ_BT * QDIM];             // 32 KB

    const int lane = threadIdx.x & 31;
    const int warp = threadIdx.x >> 5;             // 0..15
    const int btile = blockIdx.x >> 3;             // 0..7
    const int dtile = blockIdx.x & 7;              // 0..7
    const int b0 = btile * PQ_BT;
    const int da = dtile * 32 + warp;              // first d
    const int db = da + 16;                        // second d

    // Cooperative load of query tile: 2048 float4 / 512 thr = 4 each
    {
        const float4* qg = reinterpret_cast<const float4*>(query + (size_t)b0 * QDIM);
        float4* sq4 = reinterpret_cast<float4*>(sq);
#pragma unroll
        for (int i = 0; i < 4; ++i)
            sq4[threadIdx.x + 512 * i] = qg[threadIdx.x + 512 * i];
    }

    // Two Wq rows register-resident (8 float4 each per lane)
    const float4* wa4 = reinterpret_cast<const float4*>(Wq + (size_t)da * QDIM);
    const float4* wb4 = reinterpret_cast<const float4*>(Wq + (size_t)db * QDIM);
    float4 wa[8], wb[8];
#pragma unroll
    for (int k = 0; k < 8; ++k) wa[k] = wa4[lane + 32 * k];
#pragma unroll
    for (int k = 0; k < 8; ++k) wb[k] = wb4[lane + 32 * k];

    __syncthreads();

#pragma unroll
    for (int bi = 0; bi < PQ_BT; ++bi) {
        const float4* q4 = reinterpret_cast<const float4*>(sq + bi * QDIM);
        float sa = 0.f, sb = 0.f;
#pragma unroll
        for (int k = 0; k < 8; ++k) {
            float4 a = q4[lane + 32 * k];
            sa += a.x * wa[k].x + a.y * wa[k].y + a.z * wa[k].z + a.w * wa[k].w;
            sb += a.x * wb[k].x + a.y * wb[k].y + a.z * wb[k].z + a.w * wb[k].w;
        }
#pragma unroll
        for (int off = 16; off > 0; off >>= 1) {
            sa += __shfl_xor_sync(0xffffffffu, sa, off);
            sb += __shfl_xor_sync(0xffffffffu, sb, off);
        }
        if (lane == 0) {
            g_pq[(b0 + bi) * ADIM + da] = sa;
            g_pq[(b0 + bi) * ADIM + db] = sb;
        }
    }
}

// ---------------------------------------------------------------------------
// Kernel 2: energies[b,t] = sum_d tanh(pq[b,d] + pm[b,t,d]) * v[d]; mask.
// One warp per (b,t) row, 16 rows per warp.
// KEY: masked rows (~50%) never touch pm — mask is read first (lanes 0..15,
// broadcast by shfl) and masked rows skip the 1 KB row load + tanh + reduce.
// Streams ~135 MB instead of 269 MB.
// mask arrives as int32 (harness normalizes bool -> int32).
// ---------------------------------------------------------------------------
#define TPW 16           // t-rows per warp
__global__ void __launch_bounds__(256) energies_kernel(
        const float* __restrict__ pm,
        const int* __restrict__ mask,
        const float* __restrict__ v) {
    const int lane = threadIdx.x & 31;
    const int warp = threadIdx.x >> 5;
    const int gw = blockIdx.x * 8 + warp;          // global warp id
    const int warpsPerB = TT / TPW;                // 256
    const int b = gw / warpsPerB;
    const int t0 = (gw % warpsPerB) * TPW;
    const size_t base = (size_t)b * TT + t0;

    // Mask for the 16 rows: lanes 0..15 load one each, broadcast later.
    int myMask = (lane < TPW) ? mask[base + lane] : 0;

    // Register-resident pq row and v (8 floats each per lane)
    const float4* pq4 = reinterpret_cast<const float4*>(g_pq + b * ADIM);
    const float4* v4 = reinterpret_cast<const float4*>(v);
    const float4 p0 = pq4[lane], p1 = pq4[lane + 32];
    const float4 v0 = v4[lane], v1 = v4[lane + 32];

#pragma unroll 2
    for (int i = 0; i < TPW; ++i) {
        const size_t idx = base + i;
        const int mk = __shfl_sync(0xffffffffu, myMask, i);

        if (mk) {                                  // masked: no pm read at all
            if (lane == 0) g_energies[idx] = MASK_VAL;
            continue;
        }

        const float4* x4 = reinterpret_cast<const float4*>(pm + idx * ADIM);
        float4 a = x4[lane];
        float4 c = x4[lane + 32];

        float s = tanh_fast(a.x + p0.x) * v0.x;
        s += tanh_fast(a.y + p0.y) * v0.y;
        s += tanh_fast(a.z + p0.z) * v0.z;
        s += tanh_fast(a.w + p0.w) * v0.w;
        s += tanh_fast(c.x + p1.x) * v1.x;
        s += tanh_fast(c.y + p1.y) * v1.y;
        s += tanh_fast(c.z + p1.z) * v1.z;
        s += tanh_fast(c.w + p1.w) * v1.w;

#pragma unroll
        for (int off = 16; off > 0; off >>= 1)
            s += __shfl_xor_sync(0xffffffffu, s, off);

        if (lane == 0)
            g_energies[idx] = s;
    }
}

// ---------------------------------------------------------------------------
// Kernel 3: row softmax over T=4096. One block (1024 thr) per batch row.
// ---------------------------------------------------------------------------
__global__ void __launch_bounds__(1024) softmax_kernel(float* __restrict__ out) {
    const int b = blockIdx.x;
    const int tid = threadIdx.x;
    const int lane = tid & 31;
    const int warp = tid >> 5;
    __shared__ float red[32];
    __shared__ float bcast;

    float e[4];
    float m = -CUDART_INF_F;
#pragma unroll
    for (int i = 0; i < 4; ++i) {
        e[i] = g_energies[(size_t)b * TT + i * 1024 + tid];
        m = fmaxf(m, e[i]);
    }
#pragma unroll
    for (int off = 16; off > 0; off >>= 1)
        m = fmaxf(m, __shfl_xor_sync(0xffffffffu, m, off));
    if (lane == 0) red[warp] = m;
    __syncthreads();
    if (warp == 0) {
        float mm = red[lane];
#pragma unroll
        for (int off = 16; off > 0; off >>= 1)
            mm = fmaxf(mm, __shfl_xor_sync(0xffffffffu, mm, off));
        if (lane == 0) bcast = mm;
    }
    __syncthreads();
    m = bcast;

    float s = 0.f;
#pragma unroll
    for (int i = 0; i < 4; ++i) {
        e[i] = __expf(e[i] - m);
        s += e[i];
    }
#pragma unroll
    for (int off = 16; off > 0; off >>= 1)
        s += __shfl_xor_sync(0xffffffffu, s, off);
    if (lane == 0) red[warp] = s;
    __syncthreads();
    if (warp == 0) {
        float ss = red[lane];
#pragma unroll
        for (int off = 16; off > 0; off >>= 1)
            ss += __shfl_xor_sync(0xffffffffu, ss, off);
        if (lane == 0) bcast = ss;
    }
    __syncthreads();
    const float inv = 1.0f / bcast;

#pragma unroll
    for (int i = 0; i < 4; ++i)
        out[(size_t)b * TT + i * 1024 + tid] = e[i] * inv;
}

// ---------------------------------------------------------------------------
extern "C" void kernel_launch(void* const* d_in, const int* in_sizes, int n_in,
                              void* d_out, int out_size) {
    const float* query = (const float*)d_in[0];          // (64, 1024) f32
    const float* pm    = (const float*)d_in[1];          // (64, 4096, 256) f32
    const int*   mask  = (const int*)d_in[2];            // (64, 4096) bool -> int32
    const float* Wq    = (const float*)d_in[3];          // (256, 1024) f32
    const float* v     = (const float*)d_in[4];          // (256,) f32
    float* out = (float*)d_out;                          // (64, 4096) f32

    // K1: (8 b-tiles) x (8 d-tiles) = 64 blocks, 512 threads
    pq_kernel<<<64, 512>>>(query, Wq);
    // K2: 64*4096/16 warps / 8 per block = 2048 blocks
    energies_kernel<<<2048, 256>>>(pm, mask, v);
    // K3: one block per batch row
    softmax_kernel<<<BB, 1024>>>(out);
}

// round 5
// speedup vs baseline: 1.4456x; 1.0224x over previous
#include <cuda_runtime.h>
#include <math_constants.h>

#define BB 64
#define TT 4096
#define QDIM 1024
#define ADIM 256
#define MASK_VAL (-1e30f)

// Scratch (allocation-free rule: device globals)
__device__ float g_pq[BB * ADIM];        // processed query (B, AD)
__device__ float g_energies[BB * TT];    // masked energies (B, T)

__device__ __forceinline__ float tanh_fast(float x) {
    float y;
    asm("tanh.approx.f32 %0, %1;" : "=f"(y) : "f"(x));
    return y;
}

// ---------------------------------------------------------------------------
// Kernel 1: pq[b,d] = dot(query[b,:], Wq[d,:])   (64 x 256, K=1024)
// Tile (8 b x 8 d), grid = 8 x 32 = 256 blocks (fills all 148 SMs).
// Block = 8 warps; warp w owns d = dtile*8 + w with its Wq row in registers
// and accumulates ALL 8 b-rows concurrently -> 8 independent FMA chains
// (ILP=8 hides the 4-cyc RAW latency that serialized the previous version).
// L2 traffic: Wq x8 + query x32 = 16 MB.
// ---------------------------------------------------------------------------
#define PQ_BT 8
__global__ void __launch_bounds__(256) pq_kernel(const float* __restrict__ query,
                                                 const float* __restrict__ Wq) {
    __shared__ float sq[PQ_BT * QDIM];             // 32 KB

    const int lane = threadIdx.x & 31;
    const int warp = threadIdx.x >> 5;             // 0..7
    const int btile = blockIdx.x >> 5;             // 0..7
    const int dtile = blockIdx.x & 31;             // 0..31
    const int b0 = btile * PQ_BT;
    const int d  = dtile * 8 + warp;

    // Wq row for this warp, register-resident (8 float4 per lane) — issued
    // before the query staging so both load streams overlap.
    const float4* w4 = reinterpret_cast<const float4*>(Wq + (size_t)d * QDIM);
    float4 w[8];
#pragma unroll
    for (int k = 0; k < 8; ++k) w[k] = w4[lane + 32 * k];

    // Cooperative load of query tile: 2048 float4 / 256 thr = 8 each
    {
        const float4* qg = reinterpret_cast<const float4*>(query + (size_t)b0 * QDIM);
        float4* sq4 = reinterpret_cast<float4*>(sq);
#pragma unroll
        for (int i = 0; i < 8; ++i)
            sq4[threadIdx.x + 256 * i] = qg[threadIdx.x + 256 * i];
    }
    __syncthreads();

    const float4* sq4 = reinterpret_cast<const float4*>(sq);
    float s[PQ_BT];
#pragma unroll
    for (int bi = 0; bi < PQ_BT; ++bi) s[bi] = 0.f;

#pragma unroll
    for (int k = 0; k < 8; ++k) {
#pragma unroll
        for (int bi = 0; bi < PQ_BT; ++bi) {
            float4 a = sq4[bi * 256 + lane + 32 * k];
            s[bi] += a.x * w[k].x + a.y * w[k].y + a.z * w[k].z + a.w * w[k].w;
        }
    }

    // 8 independent 32-lane reductions, shfl latency overlapped across bi.
#pragma unroll
    for (int off = 16; off > 0; off >>= 1) {
#pragma unroll
        for (int bi = 0; bi < PQ_BT; ++bi)
            s[bi] += __shfl_xor_sync(0xffffffffu, s[bi], off);
    }
    if (lane == 0) {
#pragma unroll
        for (int bi = 0; bi < PQ_BT; ++bi)
            g_pq[(b0 + bi) * ADIM + d] = s[bi];
    }
}

// ---------------------------------------------------------------------------
// Kernel 2: energies[b,t] = sum_d tanh(pq[b,d] + pm[b,t,d]) * v[d]; mask.
// One warp per 16 t-rows. Masked rows (~50%) never touch pm.
// Mask bits are balloted once; masked outputs written upfront (coalesced);
// unmasked rows processed TWO at a time via __fns -> 4 LDG.128 in flight
// per warp and two interleaved reduction chains (no per-row branch).
// pm is read with __ldcs (streaming; 268 MB read-once must not thrash L2).
// mask arrives as int32 (harness normalizes bool -> int32).
// ---------------------------------------------------------------------------
#define TPW 16           // t-rows per warp
__global__ void __launch_bounds__(256) energies_kernel(
        const float* __restrict__ pm,
        const int* __restrict__ mask,
        const float* __restrict__ v) {
    const int lane = threadIdx.x & 31;
    const int warp = threadIdx.x >> 5;
    const int gw = blockIdx.x * 8 + warp;          // global warp id
    const int warpsPerB = TT / TPW;                // 256
    const int b = gw / warpsPerB;
    const int t0 = (gw % warpsPerB) * TPW;
    const size_t base = (size_t)b * TT + t0;

    // Mask for the 16 rows: lanes 0..15 load one each.
    const int myMask = (lane < TPW) ? mask[base + lane] : 1;
    const unsigned bits = __ballot_sync(0xffffffffu, (lane < TPW) && (myMask == 0));

    // Masked rows: write MASK_VAL upfront, coalesced, no reduction needed.
    if (lane < TPW && myMask)
        g_energies[base + lane] = MASK_VAL;

    const int n = __popc(bits);
    if (n == 0) return;

    // Register-resident pq row and v (8 floats each per lane)
    const float4* pq4 = reinterpret_cast<const float4*>(g_pq + b * ADIM);
    const float4* v4 = reinterpret_cast<const float4*>(v);
    const float4 p0 = pq4[lane], p1 = pq4[lane + 32];
    const float4 v0 = v4[lane], v1 = v4[lane + 32];

    for (int j = 0; j < n; j += 2) {
        const int i0 = __fns(bits, 0, j + 1);
        const bool has1 = (j + 1 < n);
        const int i1 = has1 ? __fns(bits, 0, j + 2) : i0;

        const float4* x0 = reinterpret_cast<const float4*>(pm + (base + i0) * ADIM);
        const float4* x1 = reinterpret_cast<const float4*>(pm + (base + i1) * ADIM);
        // 4 independent 128B loads in flight
        float4 a0 = __ldcs(x0 + lane);
        float4 c0 = __ldcs(x0 + lane + 32);
        float4 a1 = __ldcs(x1 + lane);
        float4 c1 = __ldcs(x1 + lane + 32);

        float s0 = tanh_fast(a0.x + p0.x) * v0.x;
        float s1 = tanh_fast(a1.x + p0.x) * v0.x;
        s0 += tanh_fast(a0.y + p0.y) * v0.y;
        s1 += tanh_fast(a1.y + p0.y) * v0.y;
        s0 += tanh_fast(a0.z + p0.z) * v0.z;
        s1 += tanh_fast(a1.z + p0.z) * v0.z;
        s0 += tanh_fast(a0.w + p0.w) * v0.w;
        s1 += tanh_fast(a1.w + p0.w) * v0.w;
        s0 += tanh_fast(c0.x + p1.x) * v1.x;
        s1 += tanh_fast(c1.x + p1.x) * v1.x;
        s0 += tanh_fast(c0.y + p1.y) * v1.y;
        s1 += tanh_fast(c1.y + p1.y) * v1.y;
        s0 += tanh_fast(c0.z + p1.z) * v1.z;
        s1 += tanh_fast(c1.z + p1.z) * v1.z;
        s0 += tanh_fast(c0.w + p1.w) * v1.w;
        s1 += tanh_fast(c1.w + p1.w) * v1.w;

#pragma unroll
        for (int off = 16; off > 0; off >>= 1) {
            s0 += __shfl_xor_sync(0xffffffffu, s0, off);
            s1 += __shfl_xor_sync(0xffffffffu, s1, off);
        }

        if (lane == 0) {
            g_energies[base + i0] = s0;
            if (has1) g_energies[base + i1] = s1;
        }
    }
}

// ---------------------------------------------------------------------------
// Kernel 3: row softmax over T=4096. One block (1024 thr) per batch row.
// ---------------------------------------------------------------------------
__global__ void __launch_bounds__(1024) softmax_kernel(float* __restrict__ out) {
    const int b = blockIdx.x;
    const int tid = threadIdx.x;
    const int lane = tid & 31;
    const int warp = tid >> 5;
    __shared__ float red[32];
    __shared__ float bcast;

    float e[4];
    float m = -CUDART_INF_F;
#pragma unroll
    for (int i = 0; i < 4; ++i) {
        e[i] = g_energies[(size_t)b * TT + i * 1024 + tid];
        m = fmaxf(m, e[i]);
    }
#pragma unroll
    for (int off = 16; off > 0; off >>= 1)
        m = fmaxf(m, __shfl_xor_sync(0xffffffffu, m, off));
    if (lane == 0) red[warp] = m;
    __syncthreads();
    if (warp == 0) {
        float mm = red[lane];
#pragma unroll
        for (int off = 16; off > 0; off >>= 1)
            mm = fmaxf(mm, __shfl_xor_sync(0xffffffffu, mm, off));
        if (lane == 0) bcast = mm;
    }
    __syncthreads();
    m = bcast;

    float s = 0.f;
#pragma unroll
    for (int i = 0; i < 4; ++i) {
        e[i] = __expf(e[i] - m);
        s += e[i];
    }
#pragma unroll
    for (int off = 16; off > 0; off >>= 1)
        s += __shfl_xor_sync(0xffffffffu, s, off);
    if (lane == 0) red[warp] = s;
    __syncthreads();
    if (warp == 0) {
        float ss = red[lane];
#pragma unroll
        for (int off = 16; off > 0; off >>= 1)
            ss += __shfl_xor_sync(0xffffffffu, ss, off);
        if (lane == 0) bcast = ss;
    }
    __syncthreads();
    const float inv = 1.0f / bcast;

#pragma unroll
    for (int i = 0; i < 4; ++i)
        out[(size_t)b * TT + i * 1024 + tid] = e[i] * inv;
}

// ---------------------------------------------------------------------------
extern "C" void kernel_launch(void* const* d_in, const int* in_sizes, int n_in,
                              void* d_out, int out_size) {
    const float* query = (const float*)d_in[0];          // (64, 1024) f32
    const float* pm    = (const float*)d_in[1];          // (64, 4096, 256) f32
    const int*   mask  = (const int*)d_in[2];            // (64, 4096) bool -> int32
    const float* Wq    = (const float*)d_in[3];          // (256, 1024) f32
    const float* v     = (const float*)d_in[4];          // (256,) f32
    float* out = (float*)d_out;                          // (64, 4096) f32

    // K1: (8 b-tiles) x (32 d-tiles) = 256 blocks, 256 threads
    pq_kernel<<<256, 256>>>(query, Wq);
    // K2: 64*4096/16 warps / 8 per block = 2048 blocks
    energies_kernel<<<2048, 256>>>(pm, mask, v);
    // K3: one block per batch row
    softmax_kernel<<<BB, 1024>>>(out);
}